// round 6
// baseline (speedup 1.0000x reference)
#include <cuda_runtime.h>
#include <cuda_bf16.h>
#include <math.h>
#include <stdint.h>

#define B_  16384
#define S_  256
#define E_  128
#define H_  128
#define NT  34

// output layout (floats): rep_vec [B,384] | log_task_prob [B,34] | latent_target [B,128] | latent_vec [B,128]
#define LP_OFF   ((size_t)B_*(S_+E_))
#define LT_OFF   (LP_OFF + (size_t)B_*NT)
#define LV_OFF   (LT_OFF + (size_t)B_*E_)

// ---------------- preconverted bf16 hi/lo + normalized-lang globals ----------------
__device__ __align__(256) __nv_bfloat16 g_s_hi[(size_t)B_*S_];
__device__ __align__(256) __nv_bfloat16 g_s_lo[(size_t)B_*S_];
__device__ __align__(256) __nv_bfloat16 g_w1_hi[(size_t)NT*H_*S_];   // [n][j][k] transposed
__device__ __align__(256) __nv_bfloat16 g_w1_lo[(size_t)NT*H_*S_];
__device__ __align__(256) __nv_bfloat16 g_w2_hi[(size_t)NT*H_*H_];
__device__ __align__(256) __nv_bfloat16 g_w2_lo[(size_t)NT*H_*H_];
__device__ __align__(256) __nv_bfloat16 g_w3_hi[(size_t)NT*E_*H_];
__device__ __align__(256) __nv_bfloat16 g_w3_lo[(size_t)NT*E_*H_];
__device__ __align__(256) float         g_lns [(size_t)B_*E_];       // lang[task_id[b]] normalized

#define NSZ  ((size_t)B_*S_)
#define N1SZ ((size_t)NT*H_*S_)
#define N2SZ ((size_t)NT*H_*H_)
#define N3SZ ((size_t)NT*E_*H_)
#define PRETOT (NSZ+N1SZ+N2SZ+N3SZ)

__global__ void preconv(const float* __restrict__ state, const float* __restrict__ W1,
                        const float* __restrict__ W2, const float* __restrict__ W3)
{
    size_t idx = (size_t)blockIdx.x*256 + threadIdx.x;
    if (idx >= PRETOT) return;
    float v; __nv_bfloat16* ph; __nv_bfloat16* pl; size_t o;
    if (idx < NSZ) {
        v = state[idx]; ph = g_s_hi; pl = g_s_lo; o = idx;
    } else if (idx < NSZ+N1SZ) {
        size_t r = idx - NSZ;
        int n = (int)(r / (H_*S_)); int rem = (int)(r % (H_*S_));
        int j = rem / S_, k = rem % S_;
        v = W1[(size_t)n*S_*H_ + (size_t)k*H_ + j];
        ph = g_w1_hi; pl = g_w1_lo; o = r;
    } else if (idx < NSZ+N1SZ+N2SZ) {
        size_t r = idx - NSZ - N1SZ;
        int n = (int)(r / (H_*H_)); int rem = (int)(r % (H_*H_));
        int j = rem / H_, k = rem % H_;
        v = W2[(size_t)n*H_*H_ + (size_t)k*H_ + j];
        ph = g_w2_hi; pl = g_w2_lo; o = r;
    } else {
        size_t r = idx - NSZ - N1SZ - N2SZ;
        int n = (int)(r / (E_*H_)); int rem = (int)(r % (E_*H_));
        int j = rem / H_, k = rem % H_;
        v = W3[(size_t)n*H_*E_ + (size_t)k*E_ + j];
        ph = g_w3_hi; pl = g_w3_lo; o = r;
    }
    __nv_bfloat16 h = __float2bfloat16_rn(v);
    float lo = v - __bfloat162float(h);
    ph[o] = h;
    pl[o] = __float2bfloat16_rn(lo);
}

__global__ void lns_kernel(const float* __restrict__ lang, const int* __restrict__ task_id)
{
    int w = (blockIdx.x*blockDim.x + threadIdx.x) >> 5;
    int lane = threadIdx.x & 31;
    if (w >= B_) return;
    int t = task_id[w];
    const float4 u = *(const float4*)(lang + (size_t)t*E_ + lane*4);
    float s = u.x*u.x + u.y*u.y + u.z*u.z + u.w*u.w;
    #pragma unroll
    for (int off = 16; off > 0; off >>= 1) s += __shfl_xor_sync(0xffffffffu, s, off);
    float il = 1.f / fmaxf(sqrtf(s), 1e-8f);
    float4 o = make_float4(u.x*il, u.y*il, u.z*il, u.w*il);
    *(float4*)(g_lns + (size_t)w*E_ + lane*4) = o;
}

// ---------------- asm helpers ----------------
__device__ __forceinline__ uint32_t smem_u32(const void* p) {
    uint32_t a;
    asm("{ .reg .u64 t; cvta.to.shared.u64 t, %1; cvt.u32.u64 %0, t; }" : "=r"(a) : "l"(p));
    return a;
}
__device__ __forceinline__ void cpa_cg(uint32_t dst, const void* src) {
    asm volatile("cp.async.cg.shared.global [%0], [%1], 16;" :: "r"(dst), "l"(src) : "memory");
}
#define CP_COMMIT() asm volatile("cp.async.commit_group;" ::: "memory")
#define CP_WAIT1()  asm volatile("cp.async.wait_group 1;" ::: "memory")

#define LDSM4(r, addr) \
    asm volatile("ldmatrix.sync.aligned.m8n8.x4.shared.b16 {%0,%1,%2,%3}, [%4];" \
        : "=r"((r)[0]), "=r"((r)[1]), "=r"((r)[2]), "=r"((r)[3]) : "r"(addr))

#define MMA16816(c, a, b) \
    asm volatile("mma.sync.aligned.m16n8k16.row.col.f32.bf16.bf16.f32 " \
        "{%0,%1,%2,%3}, {%4,%5,%6,%7}, {%8,%9}, {%0,%1,%2,%3};" \
        : "+f"((c)[0]), "+f"((c)[1]), "+f"((c)[2]), "+f"((c)[3]) \
        : "r"((a)[0]), "r"((a)[1]), "r"((a)[2]), "r"((a)[3]), "r"((b)[0]), "r"((b)[1]))

// ---------------- SMEM map (bytes from dynamic base) ----------------
#define CH    0        // 2 bufs x 4 mats(A_hi,A_lo,B_hi,B_lo) x 16384 = 131072
#define ACT   131072   // act_hi [2 panels x 16384] ; act_lo at +32768
#define RED   196608   // [4 colgroups][128 rows][2] floats = 4096
#define PWB   200704   // 128 floats
#define IQB   201216
#define TGB   201728   // 128 ints
#define BIA   202240   // 3 x 128 floats
#define SMEM_TOTAL 203776

#define NTHR 512

__device__ __forceinline__ void issue_loads(int n, int s, int c, uint32_t dstbase,
                                            int tid, int b0)
{
    if (n >= NT) return;
    const int kw0 = c * 64;
    const int Kfull = (s == 0) ? S_ : H_;
    const __nv_bfloat16 *wh, *wl;
    if (s == 0)      { wh = g_w1_hi + (size_t)n*H_*S_; wl = g_w1_lo + (size_t)n*H_*S_; }
    else if (s == 1) { wh = g_w2_hi + (size_t)n*H_*H_; wl = g_w2_lo + (size_t)n*H_*H_; }
    else             { wh = g_w3_hi + (size_t)n*E_*H_; wl = g_w3_lo + (size_t)n*E_*H_; }
    #pragma unroll
    for (int i = 0; i < 2; i++) {
        int u = tid + i*NTHR;                 // 0..1023
        int j = u >> 3, kb = u & 7;
        uint32_t sw = (uint32_t)(u*16);
        sw = sw ^ ((sw >> 3) & 0x70);
        size_t so = (size_t)j*Kfull + kw0 + kb*8;
        cpa_cg(dstbase + 32768 + sw, wh + so);
        cpa_cg(dstbase + 49152 + sw, wl + so);
        if (s == 0) {
            size_t ao = (size_t)(b0 + j)*S_ + kw0 + kb*8;
            cpa_cg(dstbase +     0 + sw, g_s_hi + ao);
            cpa_cg(dstbase + 16384 + sw, g_s_lo + ao);
        }
    }
}

// 32x32 warp tile, pass-major MMA ordering (dependent MMAs 8 apart)
__device__ __forceinline__ void mma_chunk(uint32_t aH, uint32_t aL, uint32_t bH, uint32_t bL,
                                          float acc[2][4][4], int lane, int RB, int CB)
{
    const uint32_t xorv = (uint32_t)((lane & 7) << 4);
    const uint32_t tA = (uint32_t)((lane >> 4) * 16);        // A k-half from lane
    const uint32_t tB = (uint32_t)(((lane >> 3) & 1) * 16);  // B k-half from lane
    uint32_t baseA[2], baseB[2];
    #pragma unroll
    for (int mt = 0; mt < 2; mt++)
        baseA[mt] = (uint32_t)((RB + mt*16 + (lane & 15)) * 128);
    #pragma unroll
    for (int np = 0; np < 2; np++)
        baseB[np] = (uint32_t)((CB + np*16 + ((lane >> 4) * 8) + (lane & 7)) * 128);

    #pragma unroll
    for (int kk = 0; kk < 4; kk++) {
        const uint32_t offA = ((uint32_t)(kk*32) + tA) ^ xorv;
        const uint32_t offB = ((uint32_t)(kk*32) + tB) ^ xorv;
        uint32_t ah[2][4], al[2][4], bh[2][4], bl[2][4];
        #pragma unroll
        for (int mt = 0; mt < 2; mt++) {
            LDSM4(ah[mt], aH + baseA[mt] + offA);
            LDSM4(al[mt], aL + baseA[mt] + offA);
        }
        #pragma unroll
        for (int np = 0; np < 2; np++) {
            LDSM4(bh[np], bH + baseB[np] + offB);
            LDSM4(bl[np], bL + baseB[np] + offB);
        }
        // pass 0: Ah * Bh   (8 independent MMAs)
        #pragma unroll
        for (int mt = 0; mt < 2; mt++)
            #pragma unroll
            for (int np = 0; np < 2; np++)
                #pragma unroll
                for (int h = 0; h < 2; h++)
                    MMA16816(acc[mt][np*2+h], ah[mt], (&bh[np][h*2]));
        // pass 1: Ah * Bl
        #pragma unroll
        for (int mt = 0; mt < 2; mt++)
            #pragma unroll
            for (int np = 0; np < 2; np++)
                #pragma unroll
                for (int h = 0; h < 2; h++)
                    MMA16816(acc[mt][np*2+h], ah[mt], (&bl[np][h*2]));
        // pass 2: Al * Bh
        #pragma unroll
        for (int mt = 0; mt < 2; mt++)
            #pragma unroll
            for (int np = 0; np < 2; np++)
                #pragma unroll
                for (int h = 0; h < 2; h++)
                    MMA16816(acc[mt][np*2+h], al[mt], (&bh[np][h*2]));
    }
}

__global__ __launch_bounds__(NTHR, 1) void enc_main(
    const float* __restrict__ state, const int* __restrict__ task_id,
    const float* __restrict__ prior,
    const float* __restrict__ b1, const float* __restrict__ b2,
    const float* __restrict__ b3, float* __restrict__ out)
{
    extern __shared__ __align__(1024) char sm[];
    const int tid  = threadIdx.x;
    const int lane = tid & 31;
    const int wid  = tid >> 5;        // 0..15
    const int RB   = (wid >> 2) * 32; // 4 row groups
    const int wn   = wid & 3;         // 4 col groups
    const int CB   = wn * 32;
    const int b0   = blockIdx.x * 128;
    const uint32_t smb = smem_u32(sm);

    float* red  = (float*)(sm + RED);
    float* pwb  = (float*)(sm + PWB);
    float* iqb  = (float*)(sm + IQB);
    int*   tgb  = (int*)  (sm + TGB);
    float* bia  = (float*)(sm + BIA);

    float acc[2][4][4];
    float lat[2][4][4];
    #pragma unroll
    for (int a = 0; a < 2; a++)
        #pragma unroll
        for (int b = 0; b < 4; b++)
            #pragma unroll
            for (int c = 0; c < 4; c++) { acc[a][b][c] = 0.f; lat[a][b][c] = 0.f; }

    // per-row (thread < 128) state
    int   trow = 0;
    float pm = 0.f, psinv = 0.f;
    float msoft = -INFINITY, ssoft = 0.f;
    if (tid < 128) {
        trow = task_id[b0 + tid];
        const float* pr = prior + (size_t)(b0 + tid) * NT;
        float m = -INFINITY;
        for (int nn = 0; nn < NT; nn++) m = fmaxf(m, pr[nn]);
        float s = 0.f;
        for (int nn = 0; nn < NT; nn++) s += expf(pr[nn] - m);
        pm = m; psinv = 1.f / s;
    }

    // prologue: prefetch chunk (n=0,s=0,c=0) into buf 0
    issue_loads(0, 0, 0, smb + CH, tid, b0);
    CP_COMMIT();
    int g = 0;

    for (int n = 0; n < NT; n++) {
        __syncthreads();   // protect BIA rewrite vs previous task's epilogue reads
        if (tid < 128) {
            bia[tid]       = b1[n*H_ + tid];
            bia[128 + tid] = b2[n*H_ + tid];
            bia[256 + tid] = b3[n*E_ + tid];
        }
        for (int s = 0; s < 3; s++) {
            const int nc = (s == 0) ? 4 : 2;
            for (int c = 0; c < nc; c++) {
                // prefetch next chunk (possibly next stage / next task)
                int cc2 = c + 1, ss2 = s, nn2 = n;
                if (cc2 == nc) { cc2 = 0; ss2 = s + 1; if (ss2 == 3) { ss2 = 0; nn2 = n + 1; } }
                issue_loads(nn2, ss2, cc2, smb + CH + (uint32_t)(((g+1)&1)*65536), tid, b0);
                CP_COMMIT();
                CP_WAIT1();
                __syncthreads();
                const uint32_t bufb = smb + CH + (uint32_t)((g&1)*65536);
                uint32_t aH, aL;
                if (s == 0) { aH = bufb; aL = bufb + 16384; }
                else        { aH = smb + ACT + (uint32_t)(c*16384); aL = aH + 32768; }
                mma_chunk(aH, aL, bufb + 32768, bufb + 49152, acc, lane, RB, CB);
                __syncthreads();
                g++;
            }

            if (s < 2) {
                // epilogue: relu(acc + bias) -> bf16 hi/lo -> act panels
                const float* bs = bia + s*128;
                #pragma unroll
                for (int mt = 0; mt < 2; mt++) {
                    const int rA = RB + mt*16 + (lane >> 2);
                    const int rB2 = rA + 8;
                    #pragma unroll
                    for (int nt = 0; nt < 4; nt++) {
                        const int col = CB + nt*8 + (lane & 3)*2;
                        float v0 = fmaxf(acc[mt][nt][0] + bs[col],   0.f);
                        float v1 = fmaxf(acc[mt][nt][1] + bs[col+1], 0.f);
                        float v2 = fmaxf(acc[mt][nt][2] + bs[col],   0.f);
                        float v3 = fmaxf(acc[mt][nt][3] + bs[col+1], 0.f);
                        acc[mt][nt][0] = 0.f; acc[mt][nt][1] = 0.f;
                        acc[mt][nt][2] = 0.f; acc[mt][nt][3] = 0.f;
                        __nv_bfloat16 h0 = __float2bfloat16_rn(v0), h1 = __float2bfloat16_rn(v1);
                        __nv_bfloat16 h2 = __float2bfloat16_rn(v2), h3 = __float2bfloat16_rn(v3);
                        __nv_bfloat16 l0 = __float2bfloat16_rn(v0 - __bfloat162float(h0));
                        __nv_bfloat16 l1 = __float2bfloat16_rn(v1 - __bfloat162float(h1));
                        __nv_bfloat16 l2 = __float2bfloat16_rn(v2 - __bfloat162float(h2));
                        __nv_bfloat16 l3 = __float2bfloat16_rn(v3 - __bfloat162float(h3));
                        const int p = col >> 6;
                        uint32_t oA = (uint32_t)(rA *128 + (col & 63)*2); oA ^= ((oA >> 3) & 0x70);
                        uint32_t oB = (uint32_t)(rB2*128 + (col & 63)*2); oB ^= ((oB >> 3) & 0x70);
                        char* basep = sm + ACT + p*16384;
                        *(uint32_t*)(basep + oA) =
                            (uint32_t)__bfloat16_as_ushort(h0) | ((uint32_t)__bfloat16_as_ushort(h1) << 16);
                        *(uint32_t*)(basep + oB) =
                            (uint32_t)__bfloat16_as_ushort(h2) | ((uint32_t)__bfloat16_as_ushort(h3) << 16);
                        *(uint32_t*)(basep + 32768 + oA) =
                            (uint32_t)__bfloat16_as_ushort(l0) | ((uint32_t)__bfloat16_as_ushort(l1) << 16);
                        *(uint32_t*)(basep + 32768 + oB) =
                            (uint32_t)__bfloat16_as_ushort(l2) | ((uint32_t)__bfloat16_as_ushort(l3) << 16);
                    }
                }
            } else {
                // ---- stage-2 epilogue ----
                const float* b3s = bia + 256;
                // pass 1: row partials for ||q||^2 and q . lang_norm
                #pragma unroll
                for (int mt = 0; mt < 2; mt++) {
                    const int rA = RB + mt*16 + (lane >> 2);
                    const int rB2 = rA + 8;
                    float nqA = 0.f, dA = 0.f, nqB = 0.f, dB = 0.f;
                    #pragma unroll
                    for (int nt = 0; nt < 4; nt++) {
                        const int col = CB + nt*8 + (lane & 3)*2;
                        const float bb0 = b3s[col], bb1 = b3s[col+1];
                        float q0 = acc[mt][nt][0] + bb0;
                        float q1 = acc[mt][nt][1] + bb1;
                        float q2 = acc[mt][nt][2] + bb0;
                        float q3 = acc[mt][nt][3] + bb1;
                        const float2 LA = *(const float2*)(g_lns + (size_t)(b0+rA)*E_ + col);
                        const float2 LB = *(const float2*)(g_lns + (size_t)(b0+rB2)*E_ + col);
                        nqA = fmaf(q0,q0, fmaf(q1,q1, nqA));
                        nqB = fmaf(q2,q2, fmaf(q3,q3, nqB));
                        dA  = fmaf(q0,LA.x, fmaf(q1,LA.y, dA));
                        dB  = fmaf(q2,LB.x, fmaf(q3,LB.y, dB));
                    }
                    #pragma unroll
                    for (int off = 1; off <= 2; off <<= 1) {
                        nqA += __shfl_xor_sync(0xffffffffu, nqA, off);
                        dA  += __shfl_xor_sync(0xffffffffu, dA,  off);
                        nqB += __shfl_xor_sync(0xffffffffu, nqB, off);
                        dB  += __shfl_xor_sync(0xffffffffu, dB,  off);
                    }
                    if ((lane & 3) == 0) {
                        *(float2*)(red + ((size_t)wn*128 + rA )*2) = make_float2(nqA, dA);
                        *(float2*)(red + ((size_t)wn*128 + rB2)*2) = make_float2(nqB, dB);
                    }
                }
                __syncthreads();
                if (tid < 128) {
                    const int r = tid;
                    float nq = 0.f, dot = 0.f;
                    #pragma unroll
                    for (int w = 0; w < 4; w++) {
                        float2 v = *(const float2*)(red + ((size_t)w*128 + r)*2);
                        nq += v.x; dot += v.y;
                    }
                    float iq = rsqrtf(nq);
                    float x = dot * iq * 10.0f;
                    float prn = prior[(size_t)(b0 + r)*NT + n];
                    float pw = expf(prn - pm) * psinv * iq;
                    float mn = fmaxf(msoft, x);
                    ssoft = ssoft * expf(msoft - mn) + expf(x - mn);
                    msoft = mn;
                    out[LP_OFF + (size_t)(b0 + r)*NT + n] = x;
                    pwb[r] = pw; iqb[r] = iq; tgb[r] = (trow == n) ? 1 : 0;
                }
                __syncthreads();
                // pass 2: latent accumulate + target scatter
                #pragma unroll
                for (int mt = 0; mt < 2; mt++) {
                    const int rA = RB + mt*16 + (lane >> 2);
                    const int rB2 = rA + 8;
                    const float pwA = pwb[rA], pwB = pwb[rB2];
                    const float iqA = iqb[rA], iqB = iqb[rB2];
                    const int tgA = tgb[rA], tgB = tgb[rB2];
                    #pragma unroll
                    for (int nt = 0; nt < 4; nt++) {
                        const int col = CB + nt*8 + (lane & 3)*2;
                        const float bb0 = b3s[col], bb1 = b3s[col+1];
                        float q0 = acc[mt][nt][0] + bb0;
                        float q1 = acc[mt][nt][1] + bb1;
                        float q2 = acc[mt][nt][2] + bb0;
                        float q3 = acc[mt][nt][3] + bb1;
                        lat[mt][nt][0] = fmaf(pwA, q0, lat[mt][nt][0]);
                        lat[mt][nt][1] = fmaf(pwA, q1, lat[mt][nt][1]);
                        lat[mt][nt][2] = fmaf(pwB, q2, lat[mt][nt][2]);
                        lat[mt][nt][3] = fmaf(pwB, q3, lat[mt][nt][3]);
                        if (tgA) *(float2*)(out + LT_OFF + (size_t)(b0+rA)*E_ + col)
                                    = make_float2(q0*iqA, q1*iqA);
                        if (tgB) *(float2*)(out + LT_OFF + (size_t)(b0+rB2)*E_ + col)
                                    = make_float2(q2*iqB, q3*iqB);
                        acc[mt][nt][0] = 0.f; acc[mt][nt][1] = 0.f;
                        acc[mt][nt][2] = 0.f; acc[mt][nt][3] = 0.f;
                    }
                }
            }
        }
    }

    // ---------------- final outputs ----------------
    if (tid < 128) {
        float lse = msoft + logf(ssoft);
        float* lp = out + LP_OFF + (size_t)(b0 + tid)*NT;
        #pragma unroll
        for (int nn = 0; nn < NT; nn++) lp[nn] -= lse;
    }
    // rep_vec state part
    for (int i = tid; i < 128*64; i += NTHR) {
        const int r = i >> 6, j = i & 63;
        float4 v = *(const float4*)(state + (size_t)(b0+r)*S_ + j*4);
        *(float4*)(out + (size_t)(b0+r)*(S_+E_) + j*4) = v;
    }
    // latent: rep_vec tail + latent_vec output, straight from register fragments
    #pragma unroll
    for (int mt = 0; mt < 2; mt++) {
        const int rA = RB + mt*16 + (lane >> 2);
        const int rB2 = rA + 8;
        #pragma unroll
        for (int nt = 0; nt < 4; nt++) {
            const int col = CB + nt*8 + (lane & 3)*2;
            float2 vA = make_float2(lat[mt][nt][0], lat[mt][nt][1]);
            float2 vB = make_float2(lat[mt][nt][2], lat[mt][nt][3]);
            *(float2*)(out + (size_t)(b0+rA )*(S_+E_) + S_ + col) = vA;
            *(float2*)(out + (size_t)(b0+rB2)*(S_+E_) + S_ + col) = vB;
            *(float2*)(out + LV_OFF + (size_t)(b0+rA )*E_ + col) = vA;
            *(float2*)(out + LV_OFF + (size_t)(b0+rB2)*E_ + col) = vB;
        }
    }
}

extern "C" void kernel_launch(void* const* d_in, const int* in_sizes, int n_in,
                              void* d_out, int out_size)
{
    (void)in_sizes; (void)n_in; (void)out_size;
    const float* state  = (const float*)d_in[0];
    const int*   tsk    = (const int*)  d_in[1];
    const float* prior  = (const float*)d_in[2];
    const float* W1     = (const float*)d_in[3];
    const float* b1     = (const float*)d_in[4];
    const float* W2     = (const float*)d_in[5];
    const float* b2     = (const float*)d_in[6];
    const float* W3     = (const float*)d_in[7];
    const float* b3     = (const float*)d_in[8];
    const float* lang   = (const float*)d_in[9];
    float* out = (float*)d_out;

    cudaFuncSetAttribute(enc_main, cudaFuncAttributeMaxDynamicSharedMemorySize, SMEM_TOTAL);

    preconv<<<(unsigned)((PRETOT + 255)/256), 256>>>(state, W1, W2, W3);
    lns_kernel<<<B_*32/256, 256>>>(lang, tsk);
    enc_main<<<B_/128, NTHR, SMEM_TOTAL>>>(state, tsk, prior, b1, b2, b3, out);
}

// round 8
// speedup vs baseline: 1.3064x; 1.3064x over previous
#include <cuda_runtime.h>
#include <math.h>
#include <stdint.h>

#define B_  16384
#define S_  256
#define E_  128
#define H_  128
#define NT  34

#define LP_OFF ((size_t)B_*(S_+E_))
#define LT_OFF (LP_OFF + (size_t)B_*NT)
#define LV_OFF (LT_OFF + (size_t)B_*E_)

__device__ __align__(256) int8_t g_sq_h[(size_t)B_*S_];
__device__ __align__(256) int8_t g_sq_l[(size_t)B_*S_];
__device__ __align__(256) float  g_ss[B_];
__device__ __align__(256) int8_t g_w1q_h[(size_t)NT*H_*S_];
__device__ __align__(256) int8_t g_w1q_l[(size_t)NT*H_*S_];
__device__ __align__(256) int8_t g_w2q_h[(size_t)NT*H_*H_];
__device__ __align__(256) int8_t g_w2q_l[(size_t)NT*H_*H_];
__device__ __align__(256) int8_t g_w3q_h[(size_t)NT*E_*H_];
__device__ __align__(256) int8_t g_w3q_l[(size_t)NT*E_*H_];
__device__ __align__(256) float  g_wsc[3*NT*128];
__device__ __align__(256) float  g_lns[(size_t)B_*E_];

__global__ void quant_state(const float* __restrict__ state)
{
    int w = (blockIdx.x*blockDim.x + threadIdx.x) >> 5;
    int lane = threadIdx.x & 31;
    if (w >= B_) return;
    const float* src = state + (size_t)w*S_;
    float v[8]; float m = 0.f;
    #pragma unroll
    for (int i = 0; i < 8; i++) { v[i] = src[lane*8 + i]; m = fmaxf(m, fabsf(v[i])); }
    #pragma unroll
    for (int off = 16; off > 0; off >>= 1) m = fmaxf(m, __shfl_xor_sync(~0u, m, off));
    m = fmaxf(m, 1e-20f);
    float sc = m*(1.f/127.f), inv = 127.f/m, inv256 = inv*256.f;
    uint32_t hw[2] = {0,0}, lw[2] = {0,0};
    #pragma unroll
    for (int i = 0; i < 8; i++) {
        int q = max(-127, min(127, __float2int_rn(v[i]*inv)));
        float r = v[i] - (float)q*sc;
        int ql = max(-127, min(127, __float2int_rn(r*inv256)));
        hw[i>>2] |= ((uint32_t)(uint8_t)(int8_t)q)  << ((i&3)*8);
        lw[i>>2] |= ((uint32_t)(uint8_t)(int8_t)ql) << ((i&3)*8);
    }
    uint32_t* dh = (uint32_t*)(g_sq_h + (size_t)w*S_ + lane*8);
    uint32_t* dl = (uint32_t*)(g_sq_l + (size_t)w*S_ + lane*8);
    dh[0] = hw[0]; dh[1] = hw[1]; dl[0] = lw[0]; dl[1] = lw[1];
    if (lane == 0) g_ss[w] = sc;
}

__global__ void quant_w(const float* __restrict__ W1, const float* __restrict__ W2,
                        const float* __restrict__ W3)
{
    int rid = (blockIdx.x*blockDim.x + threadIdx.x) >> 5;
    int lane = threadIdx.x & 31;
    if (rid >= 3*NT*128) return;
    int s = rid / (NT*128);
    int r2 = rid % (NT*128);
    int n = r2 >> 7, j = r2 & 127;
    int K; const float* W; int8_t* dh; int8_t* dl;
    if (s == 0)      { K = S_; W = W1; dh = g_w1q_h; dl = g_w1q_l; }
    else if (s == 1) { K = H_; W = W2; dh = g_w2q_h; dl = g_w2q_l; }
    else             { K = H_; W = W3; dh = g_w3q_h; dl = g_w3q_l; }
    const int kpl = K / 32;
    float v[8]; float m = 0.f;
    #pragma unroll
    for (int i = 0; i < 8; i++) {
        if (i < kpl) { v[i] = W[((size_t)n*K + lane*kpl + i)*128 + j]; m = fmaxf(m, fabsf(v[i])); }
        else v[i] = 0.f;
    }
    #pragma unroll
    for (int off = 16; off > 0; off >>= 1) m = fmaxf(m, __shfl_xor_sync(~0u, m, off));
    m = fmaxf(m, 1e-20f);
    float sc = m*(1.f/127.f), inv = 127.f/m, inv256 = inv*256.f;
    uint32_t hw[2] = {0,0}, lw[2] = {0,0};
    #pragma unroll
    for (int i = 0; i < 8; i++) {
        if (i < kpl) {
            int q = max(-127, min(127, __float2int_rn(v[i]*inv)));
            float r = v[i] - (float)q*sc;
            int ql = max(-127, min(127, __float2int_rn(r*inv256)));
            hw[i>>2] |= ((uint32_t)(uint8_t)(int8_t)q)  << ((i&3)*8);
            lw[i>>2] |= ((uint32_t)(uint8_t)(int8_t)ql) << ((i&3)*8);
        }
    }
    size_t ro = (size_t)(n*128 + j)*K + lane*kpl;
    ((uint32_t*)(dh + ro))[0] = hw[0];
    ((uint32_t*)(dl + ro))[0] = lw[0];
    if (kpl == 8) {
        ((uint32_t*)(dh + ro))[1] = hw[1];
        ((uint32_t*)(dl + ro))[1] = lw[1];
    }
    if (lane == 0) g_wsc[rid] = sc;
}

__global__ void lns_kernel(const float* __restrict__ lang, const int* __restrict__ task_id)
{
    int w = (blockIdx.x*blockDim.x + threadIdx.x) >> 5;
    int lane = threadIdx.x & 31;
    if (w >= B_) return;
    int t = task_id[w];
    const float4 u = *(const float4*)(lang + (size_t)t*E_ + lane*4);
    float s = u.x*u.x + u.y*u.y + u.z*u.z + u.w*u.w;
    #pragma unroll
    for (int off = 16; off > 0; off >>= 1) s += __shfl_xor_sync(~0u, s, off);
    float il = 1.f / fmaxf(sqrtf(s), 1e-8f);
    *(float4*)(g_lns + (size_t)w*E_ + lane*4) = make_float4(u.x*il, u.y*il, u.z*il, u.w*il);
}

__device__ __forceinline__ uint32_t smem_u32(const void* p) {
    uint32_t a;
    asm("{ .reg .u64 t; cvta.to.shared.u64 t, %1; cvt.u32.u64 %0, t; }" : "=r"(a) : "l"(p));
    return a;
}
__device__ __forceinline__ void cpa_cg(uint32_t dst, const void* src) {
    asm volatile("cp.async.cg.shared.global [%0], [%1], 16;" :: "r"(dst), "l"(src) : "memory");
}
#define CP_COMMIT() asm volatile("cp.async.commit_group;" ::: "memory")
#define CP_WAIT1()  asm volatile("cp.async.wait_group 1;" ::: "memory")
#define LDSM4(r, addr) \
    asm volatile("ldmatrix.sync.aligned.m8n8.x4.shared.b16 {%0,%1,%2,%3}, [%4];" \
        : "=r"((r)[0]), "=r"((r)[1]), "=r"((r)[2]), "=r"((r)[3]) : "r"(addr))
#define IMMA(c, a, bb0, bb1) \
    asm volatile("mma.sync.aligned.m16n8k32.row.col.s32.s8.s8.s32 " \
        "{%0,%1,%2,%3}, {%4,%5,%6,%7}, {%8,%9}, {%0,%1,%2,%3};" \
        : "+r"((c)[0]), "+r"((c)[1]), "+r"((c)[2]), "+r"((c)[3]) \
        : "r"((a)[0]), "r"((a)[1]), "r"((a)[2]), "r"((a)[3]), "r"(bb0), "r"(bb1))
#define SW(o) ((o) ^ (((o) >> 3) & 0x70))

#define SST   0
#define WB    65536
#define ACT   131072
#define RED   163840
#define PWB   167936
#define IQB   168448
#define TGB   168960
#define BIA   169472
#define SBV   171008
#define SSV   172544
#define ASC1  173056
#define IASC1 173568
#define ASC2  174080
#define IASC2 174592
#define SMEM_TOTAL 175104
#define NTHR 256

__device__ __forceinline__ void issue_w(int n, int s, int c, uint32_t dst, int tid)
{
    if (n >= NT) return;
    const int8_t* h; const int8_t* l; int stride;
    if (s == 0)      { h = g_w1q_h + (size_t)n*H_*S_ + c*128; l = g_w1q_l + (size_t)n*H_*S_ + c*128; stride = S_; }
    else if (s == 1) { h = g_w2q_h + (size_t)n*H_*H_; l = g_w2q_l + (size_t)n*H_*H_; stride = H_; }
    else             { h = g_w3q_h + (size_t)n*E_*H_; l = g_w3q_l + (size_t)n*E_*H_; stride = H_; }
    #pragma unroll
    for (int i = 0; i < 4; i++) {
        int u = tid + i*NTHR;
        int j = u >> 3, kb = u & 7;
        uint32_t swo = SW((uint32_t)(u*16));
        cpa_cg(dst + swo,         h + (size_t)j*stride + kb*16);
        cpa_cg(dst + 16384 + swo, l + (size_t)j*stride + kb*16);
    }
}

__device__ __forceinline__ void mma_i8(uint32_t aBase, uint32_t bBase,
                                       int acc1[4][4][4], int acc2[4][4][4],
                                       int lane, int RB, int CB)
{
    const uint32_t xorv = (uint32_t)((lane & 7) << 4);
    const uint32_t rsel = (uint32_t)(lane & 15);
    const uint32_t ksel = (uint32_t)((lane >> 4) * 16);
    #pragma unroll
    for (int kk = 0; kk < 4; kk++) {
        const uint32_t koff = ((uint32_t)(kk*32) + ksel) ^ xorv;
        #pragma unroll
        for (int np = 0; np < 2; np++) {
            uint32_t bh[4], bl[4];
            uint32_t ba = bBase + (uint32_t)((CB + np*16 + rsel) * 128) + koff;
            LDSM4(bh, ba);
            LDSM4(bl, ba + 16384);
            #pragma unroll
            for (int mt = 0; mt < 4; mt++) {
                uint32_t ah[4], al[4];
                uint32_t aa = aBase + (uint32_t)((RB + mt*16 + rsel) * 128) + koff;
                LDSM4(ah, aa);
                LDSM4(al, aa + 16384);
                IMMA(acc1[mt][np*2+0], ah, bh[0], bh[2]);
                IMMA(acc1[mt][np*2+1], ah, bh[1], bh[3]);
                IMMA(acc2[mt][np*2+0], ah, bl[0], bl[2]);
                IMMA(acc2[mt][np*2+1], ah, bl[1], bl[3]);
                IMMA(acc2[mt][np*2+0], al, bh[0], bh[2]);
                IMMA(acc2[mt][np*2+1], al, bh[1], bh[3]);
            }
        }
    }
}

__global__ __launch_bounds__(NTHR, 1) void enc_main(
    const float* __restrict__ state, const int* __restrict__ task_id,
    const float* __restrict__ prior,
    const float* __restrict__ b1, const float* __restrict__ b2,
    const float* __restrict__ b3, float* __restrict__ out)
{
    extern __shared__ __align__(1024) char sm[];
    const int tid  = threadIdx.x;
    const int lane = tid & 31;
    const int wid  = tid >> 5;
    const int RB   = (wid >> 2) * 64;
    const int wn   = wid & 3;
    const int CB   = wn * 32;
    const int b0   = blockIdx.x * 128;
    const uint32_t smb = smem_u32(sm);

    float* red   = (float*)(sm + RED);
    float* pwb   = (float*)(sm + PWB);
    float* iqb   = (float*)(sm + IQB);
    int*   tgb   = (int*)  (sm + TGB);
    float* bia   = (float*)(sm + BIA);
    float* sbv   = (float*)(sm + SBV);
    float* ssv   = (float*)(sm + SSV);
    float* asc1  = (float*)(sm + ASC1);
    float* iasc1 = (float*)(sm + IASC1);
    float* asc2  = (float*)(sm + ASC2);
    float* iasc2 = (float*)(sm + IASC2);

    int   acc1[4][4][4];
    int   acc2[4][4][4];
    float lat [4][4][4];
    #pragma unroll
    for (int a = 0; a < 4; a++)
        #pragma unroll
        for (int b = 0; b < 4; b++)
            #pragma unroll
            for (int c = 0; c < 4; c++) { acc1[a][b][c] = 0; acc2[a][b][c] = 0; lat[a][b][c] = 0.f; }

    int   trow = 0;
    float pm = 0.f, psinv = 0.f;
    float msoft = -INFINITY, ssoft = 0.f;
    if (tid < 128) {
        trow = task_id[b0 + tid];
        const float* pr = prior + (size_t)(b0 + tid) * NT;
        float m = -INFINITY;
        for (int nn = 0; nn < NT; nn++) m = fmaxf(m, pr[nn]);
        float s = 0.f;
        for (int nn = 0; nn < NT; nn++) s += expf(pr[nn] - m);
        pm = m; psinv = 1.f / s;
        ssv[tid] = g_ss[b0 + tid];
    }

    #pragma unroll
    for (int c = 0; c < 2; c++)
        #pragma unroll
        for (int i = 0; i < 4; i++) {
            int u = tid + i*NTHR;
            int j = u >> 3, kb = u & 7;
            uint32_t swo = SW((uint32_t)(u*16));
            cpa_cg(smb + SST + c*32768 + swo,         g_sq_h + (size_t)(b0+j)*S_ + c*128 + kb*16);
            cpa_cg(smb + SST + c*32768 + 16384 + swo, g_sq_l + (size_t)(b0+j)*S_ + c*128 + kb*16);
        }
    CP_COMMIT();
    issue_w(0, 0, 0, smb + WB, tid);
    CP_COMMIT();
    int g = 0;

    for (int n = 0; n < NT; n++) {
        __syncthreads();
        if (tid < 128) {
            bia[tid]       = b1[n*H_ + tid];
            bia[128 + tid] = b2[n*H_ + tid];
            bia[256 + tid] = b3[n*E_ + tid];
            sbv[tid]       = g_wsc[0*NT*128 + n*128 + tid];
            sbv[128 + tid] = g_wsc[1*NT*128 + n*128 + tid];
            sbv[256 + tid] = g_wsc[2*NT*128 + n*128 + tid];
        }
        for (int s = 0; s < 3; s++) {
            const int nc = (s == 0) ? 2 : 1;
            for (int c = 0; c < nc; c++) {
                int cc2 = c + 1, ss2 = s, nn2 = n;
                if (cc2 == nc) { cc2 = 0; ss2 = s + 1; if (ss2 == 3) { ss2 = 0; nn2 = n + 1; } }
                issue_w(nn2, ss2, cc2, smb + WB + (uint32_t)(((g+1)&1)*32768), tid);
                CP_COMMIT();
                CP_WAIT1();
                __syncthreads();
                uint32_t aB = (s == 0) ? (smb + SST + (uint32_t)(c*32768)) : (smb + ACT);
                mma_i8(aB, smb + WB + (uint32_t)((g&1)*32768), acc1, acc2, lane, RB, CB);
                __syncthreads();
                g++;
            }

            if (s < 2) {
                const float* bs = bia + s*128;
                const float* sb = sbv + s*128;
                const float* saArr = (s == 0) ? ssv : asc1;
                float* oasc  = (s == 0) ? asc1 : asc2;
                float* oiasc = (s == 0) ? iasc1 : iasc2;
                #pragma unroll
                for (int mt = 0; mt < 4; mt++) {
                    const int rA = RB + mt*16 + (lane >> 2);
                    const int rB2 = rA + 8;
                    const float saA = saArr[rA], saB = saArr[rB2];
                    float mA = 0.f, mB = 0.f;
                    #pragma unroll
                    for (int nt = 0; nt < 4; nt++) {
                        const int col = CB + nt*8 + (lane & 3)*2;
                        float t0 = (float)acc1[mt][nt][0] + (float)acc2[mt][nt][0]*0.00390625f;
                        float t1 = (float)acc1[mt][nt][1] + (float)acc2[mt][nt][1]*0.00390625f;
                        float t2 = (float)acc1[mt][nt][2] + (float)acc2[mt][nt][2]*0.00390625f;
                        float t3 = (float)acc1[mt][nt][3] + (float)acc2[mt][nt][3]*0.00390625f;
                        float v0 = fmaxf(fmaf(t0, saA*sb[col],   bs[col]),   0.f);
                        float v1 = fmaxf(fmaf(t1, saA*sb[col+1], bs[col+1]), 0.f);
                        float v2 = fmaxf(fmaf(t2, saB*sb[col],   bs[col]),   0.f);
                        float v3 = fmaxf(fmaf(t3, saB*sb[col+1], bs[col+1]), 0.f);
                        mA = fmaxf(mA, fmaxf(v0, v1));
                        mB = fmaxf(mB, fmaxf(v2, v3));
                        acc1[mt][nt][0] = __float_as_int(v0);
                        acc1[mt][nt][1] = __float_as_int(v1);
                        acc1[mt][nt][2] = __float_as_int(v2);
                        acc1[mt][nt][3] = __float_as_int(v3);
                    }
                    mA = fmaxf(mA, __shfl_xor_sync(~0u, mA, 1));
                    mA = fmaxf(mA, __shfl_xor_sync(~0u, mA, 2));
                    mB = fmaxf(mB, __shfl_xor_sync(~0u, mB, 1));
                    mB = fmaxf(mB, __shfl_xor_sync(~0u, mB, 2));
                    if ((lane & 3) == 0) { red[wn*128 + rA] = mA; red[wn*128 + rB2] = mB; }
                }
                __syncthreads();
                if (tid < 128) {
                    float m = fmaxf(fmaxf(red[tid], red[128 + tid]),
                                    fmaxf(red[256 + tid], red[384 + tid]));
                    m = fmaxf(m, 1e-20f);
                    oasc[tid]  = m * (1.f/127.f);
                    oiasc[tid] = 127.f / m;
                }
                __syncthreads();
                #pragma unroll
                for (int mt = 0; mt < 4; mt++) {
                    const int rA = RB + mt*16 + (lane >> 2);
                    const int rB2 = rA + 8;
                    const float iA = oiasc[rA], iB = oiasc[rB2];
                    const float scA = oasc[rA], scB = oasc[rB2];
                    #pragma unroll
                    for (int nt = 0; nt < 4; nt++) {
                        const int col = CB + nt*8 + (lane & 3)*2;
                        float v0 = __int_as_float(acc1[mt][nt][0]);
                        float v1 = __int_as_float(acc1[mt][nt][1]);
                        float v2 = __int_as_float(acc1[mt][nt][2]);
                        float v3 = __int_as_float(acc1[mt][nt][3]);
                        int q0 = min(127, __float2int_rn(v0*iA));
                        int q1 = min(127, __float2int_rn(v1*iA));
                        int q2 = min(127, __float2int_rn(v2*iB));
                        int q3 = min(127, __float2int_rn(v3*iB));
                        int l0 = max(-127, min(127, __float2int_rn((v0 - q0*scA)*iA*256.f)));
                        int l1 = max(-127, min(127, __float2int_rn((v1 - q1*scA)*iA*256.f)));
                        int l2 = max(-127, min(127, __float2int_rn((v2 - q2*scB)*iB*256.f)));
                        int l3 = max(-127, min(127, __float2int_rn((v3 - q3*scB)*iB*256.f)));
                        uint32_t oA = SW((uint32_t)(rA*128 + col));
                        uint32_t oB = SW((uint32_t)(rB2*128 + col));
                        *(uint16_t*)(sm + ACT + oA) = (uint16_t)((uint8_t)q0 | ((uint16_t)(uint8_t)q1 << 8));
                        *(uint16_t*)(sm + ACT + oB) = (uint16_t)((uint8_t)q2 | ((uint16_t)(uint8_t)q3 << 8));
                        *(uint16_t*)(sm + ACT + 16384 + oA) = (uint16_t)((uint8_t)l0 | ((uint16_t)(uint8_t)l1 << 8));
                        *(uint16_t*)(sm + ACT + 16384 + oB) = (uint16_t)((uint8_t)l2 | ((uint16_t)(uint8_t)l3 << 8));
                        acc1[mt][nt][0] = 0; acc1[mt][nt][1] = 0; acc1[mt][nt][2] = 0; acc1[mt][nt][3] = 0;
                        acc2[mt][nt][0] = 0; acc2[mt][nt][1] = 0; acc2[mt][nt][2] = 0; acc2[mt][nt][3] = 0;
                    }
                }
            } else {
                const float* bs = bia + 256;
                const float* sb = sbv + 256;
                #pragma unroll
                for (int mt = 0; mt < 4; mt++) {
                    const int rA = RB + mt*16 + (lane >> 2);
                    const int rB2 = rA + 8;
                    const float saA = asc2[rA], saB = asc2[rB2];
                    float nqA = 0.f, dA = 0.f, nqB = 0.f, dB = 0.f;
                    #pragma unroll
                    for (int nt = 0; nt < 4; nt++) {
                        const int col = CB + nt*8 + (lane & 3)*2;
                        float t0 = (float)acc1[mt][nt][0] + (float)acc2[mt][nt][0]*0.00390625f;
                        float t1 = (float)acc1[mt][nt][1] + (float)acc2[mt][nt][1]*0.00390625f;
                        float t2 = (float)acc1[mt][nt][2] + (float)acc2[mt][nt][2]*0.00390625f;
                        float t3 = (float)acc1[mt][nt][3] + (float)acc2[mt][nt][3]*0.00390625f;
                        float q0 = fmaf(t0, saA*sb[col],   bs[col]);
                        float q1 = fmaf(t1, saA*sb[col+1], bs[col+1]);
                        float q2 = fmaf(t2, saB*sb[col],   bs[col]);
                        float q3 = fmaf(t3, saB*sb[col+1], bs[col+1]);
                        const float2 LA = *(const float2*)(g_lns + (size_t)(b0+rA)*E_ + col);
                        const float2 LB = *(const float2*)(g_lns + (size_t)(b0+rB2)*E_ + col);
                        nqA = fmaf(q0,q0, fmaf(q1,q1, nqA));
                        nqB = fmaf(q2,q2, fmaf(q3,q3, nqB));
                        dA  = fmaf(q0,LA.x, fmaf(q1,LA.y, dA));
                        dB  = fmaf(q2,LB.x, fmaf(q3,LB.y, dB));
                        acc1[mt][nt][0] = __float_as_int(q0);
                        acc1[mt][nt][1] = __float_as_int(q1);
                        acc1[mt][nt][2] = __float_as_int(q2);
                        acc1[mt][nt][3] = __float_as_int(q3);
                    }
                    #pragma unroll
                    for (int off = 1; off <= 2; off <<= 1) {
                        nqA += __shfl_xor_sync(~0u, nqA, off);
                        dA  += __shfl_xor_sync(~0u, dA,  off);
                        nqB += __shfl_xor_sync(~0u, nqB, off);
                        dB  += __shfl_xor_sync(~0u, dB,  off);
                    }
                    if ((lane & 3) == 0) {
                        *(float2*)(red + ((size_t)wn*128 + rA )*2) = make_float2(nqA, dA);
                        *(float2*)(red + ((size_t)wn*128 + rB2)*2) = make_float2(nqB, dB);
                    }
                }
                __syncthreads();
                if (tid < 128) {
                    float nq = 0.f, dot = 0.f;
                    #pragma unroll
                    for (int w = 0; w < 4; w++) {
                        float2 v = *(const float2*)(red + ((size_t)w*128 + tid)*2);
                        nq += v.x; dot += v.y;
                    }
                    float iq = rsqrtf(nq);
                    float x = dot * iq * 10.0f;
                    float prn = prior[(size_t)(b0 + tid)*NT + n];
                    float pw = expf(prn - pm) * psinv * iq;
                    float mn = fmaxf(msoft, x);
                    ssoft = ssoft * expf(msoft - mn) + expf(x - mn);
                    msoft = mn;
                    out[LP_OFF + (size_t)(b0 + tid)*NT + n] = x;
                    pwb[tid] = pw; iqb[tid] = iq; tgb[tid] = (trow == n) ? 1 : 0;
                }
                __syncthreads();
                #pragma unroll
                for (int mt = 0; mt < 4; mt++) {
                    const int rA = RB + mt*16 + (lane >> 2);
                    const int rB2 = rA + 8;
                    const float pwA = pwb[rA], pwB = pwb[rB2];
                    const float iqA = iqb[rA], iqB = iqb[rB2];
                    const int tgA = tgb[rA], tgB = tgb[rB2];
                    #pragma unroll
                    for (int nt = 0; nt < 4; nt++) {
                        const int col = CB + nt*8 + (lane & 3)*2;
                        float q0 = __int_as_float(acc1[mt][nt][0]);
                        float q1 = __int_as_float(acc1[mt][nt][1]);
                        float q2 = __int_as_float(acc1[mt][nt][2]);
                        float q3 = __int_as_float(acc1[mt][nt][3]);
                        lat[mt][nt][0] = fmaf(pwA, q0, lat[mt][nt][0]);
                        lat[mt][nt][1] = fmaf(pwA, q1, lat[mt][nt][1]);
                        lat[mt][nt][2] = fmaf(pwB, q2, lat[mt][nt][2]);
                        lat[mt][nt][3] = fmaf(pwB, q3, lat[mt][nt][3]);
                        if (tgA) *(float2*)(out + LT_OFF + (size_t)(b0+rA)*E_ + col)
                                    = make_float2(q0*iqA, q1*iqA);
                        if (tgB) *(float2*)(out + LT_OFF + (size_t)(b0+rB2)*E_ + col)
                                    = make_float2(q2*iqB, q3*iqB);
                        acc1[mt][nt][0] = 0; acc1[mt][nt][1] = 0; acc1[mt][nt][2] = 0; acc1[mt][nt][3] = 0;
                        acc2[mt][nt][0] = 0; acc2[mt][nt][1] = 0; acc2[mt][nt][2] = 0; acc2[mt][nt][3] = 0;
                    }
                }
            }
        }
    }

    if (tid < 128) {
        float lse = msoft + logf(ssoft);
        float* lp = out + LP_OFF + (size_t)(b0 + tid)*NT;
        #pragma unroll
        for (int nn = 0; nn < NT; nn++) lp[nn] -= lse;
    }
    for (int i = tid; i < 128*64; i += NTHR) {
        const int r = i >> 6, j = i & 63;
        float4 v = *(const float4*)(state + (size_t)(b0+r)*S_ + j*4);
        *(float4*)(out + (size_t)(b0+r)*(S_+E_) + j*4) = v;
    }
    #pragma unroll
    for (int mt = 0; mt < 4; mt++) {
        const int rA = RB + mt*16 + (lane >> 2);
        const int rB2 = rA + 8;
        #pragma unroll
        for (int nt = 0; nt < 4; nt++) {
            const int col = CB + nt*8 + (lane & 3)*2;
            float2 vA = make_float2(lat[mt][nt][0], lat[mt][nt][1]);
            float2 vB = make_float2(lat[mt][nt][2], lat[mt][nt][3]);
            *(float2*)(out + (size_t)(b0+rA )*(S_+E_) + S_ + col) = vA;
            *(float2*)(out + (size_t)(b0+rB2)*(S_+E_) + S_ + col) = vB;
            *(float2*)(out + LV_OFF + (size_t)(b0+rA )*E_ + col) = vA;
            *(float2*)(out + LV_OFF + (size_t)(b0+rB2)*E_ + col) = vB;
        }
    }
}

extern "C" void kernel_launch(void* const* d_in, const int* in_sizes, int n_in,
                              void* d_out, int out_size)
{
    (void)in_sizes; (void)n_in; (void)out_size;
    const float* state  = (const float*)d_in[0];
    const int*   tsk    = (const int*)  d_in[1];
    const float* prior  = (const float*)d_in[2];
    const float* W1     = (const float*)d_in[3];
    const float* b1     = (const float*)d_in[4];
    const float* W2     = (const float*)d_in[5];
    const float* b2     = (const float*)d_in[6];
    const float* W3     = (const float*)d_in[7];
    const float* b3     = (const float*)d_in[8];
    const float* lang   = (const float*)d_in[9];
    float* out = (float*)d_out;

    cudaFuncSetAttribute(enc_main, cudaFuncAttributeMaxDynamicSharedMemorySize, SMEM_TOTAL);

    quant_state<<<2048, 256>>>(state);
    quant_w<<<(3*NT*128*32 + 255)/256, 256>>>(W1, W2, W3);
    lns_kernel<<<2048, 256>>>(lang, tsk);
    enc_main<<<B_/128, NTHR, SMEM_TOTAL>>>(state, tsk, prior, b1, b2, b3, out);
}